// round 15
// baseline (speedup 1.0000x reference)
#include <cuda_runtime.h>
#include <math.h>

#define HH 64
#define WW 64
#define BATCH 2
#define CCH 128
#define NPIX (BATCH*HH*WW)
#define KA 624   // unified K: 496 score cols (4cc x 124) + 128 q cols
#define GK 16    // GEMM K-chunk

// ---- scratch ----
__device__ float g_A[(size_t)NPIX * KA];   // [pixel][0..495: scores, 496..623: q]
__device__ float g_Bd[(size_t)KA * 256];   // B duplicated+slot-permuted: see prep
__device__ float g_m2p[8 * CCH * CCH];     // split-K partials (8-way)

// Slot permutation: logical col c (0..127) -> float pos of its dup-pair.
// Inner loop lane tx, read r reads f4 slot r*16+tx which must hold pairs for
// n = (r>=2)*64 + tx*4 + (r&1)*2 + {0,1}.
__device__ __forceinline__ int dup_fpos(int c) {
    int hi = c >> 6, t4 = (c & 63) >> 2, rb = (c >> 1) & 1, lo = c & 1;
    return (2 * hi + rb) * 64 + t4 * 4 + lo * 2;
}

// ============================================================
// Prep A: permute W rows (s=4p+cc -> s'=cc*124+p) into g_Bd, duplicated.
// ============================================================
__global__ __launch_bounds__(256) void prep_permute(const float* __restrict__ W) {
    int gid = blockIdx.x * 256 + threadIdx.x;     // < 63488
    int row = gid >> 7, c = gid & 127;
    int cc = row / 124, p = row - cc * 124;
    float v = (p < 121) ? W[(size_t)(4 * p + cc) * CCH + c] : 0.f;
    *(float2*)&g_Bd[(size_t)row * 256 + dup_fpos(c)] = make_float2(v, v);
}

// ============================================================
// Prep B: M2 partials (8-way split-K) + combine into g_Bd rows 496..623.
// ============================================================
__global__ __launch_bounds__(128) void prep_m2_partial(const float* __restrict__ W,
                                                       const float* __restrict__ pos) {
    int o = threadIdx.x;
    int ks = blockIdx.x, c = blockIdx.y;       // grid (8, 128)
    int g = c >> 5, cm = c & 31;
    int s0 = 121 * g;
    int pbeg = ks * 16;
    int pend = (pbeg + 16 < 121) ? pbeg + 16 : 121;

    float a0 = 0.f, a1 = 0.f, a2 = 0.f, a3 = 0.f;
    int p = pbeg;
    for (; p + 4 <= pend; p += 4) {
        a0 += pos[(s0 + p + 0) * 32 + cm] * W[(size_t)(s0 + p + 0) * CCH + o];
        a1 += pos[(s0 + p + 1) * 32 + cm] * W[(size_t)(s0 + p + 1) * CCH + o];
        a2 += pos[(s0 + p + 2) * 32 + cm] * W[(size_t)(s0 + p + 2) * CCH + o];
        a3 += pos[(s0 + p + 3) * 32 + cm] * W[(size_t)(s0 + p + 3) * CCH + o];
    }
    for (; p < pend; p++)
        a0 += pos[(s0 + p) * 32 + cm] * W[(size_t)(s0 + p) * CCH + o];
    g_m2p[((size_t)ks * CCH + c) * CCH + o] = (a0 + a1) + (a2 + a3);
}

__global__ __launch_bounds__(256) void prep_m2_combine() {
    int i = blockIdx.x * 256 + threadIdx.x;       // 0..16383
    float s01 = g_m2p[i]             + g_m2p[16384 + i];
    float s23 = g_m2p[32768 + i]     + g_m2p[49152 + i];
    float s45 = g_m2p[65536 + i]     + g_m2p[81920 + i];
    float s67 = g_m2p[98304 + i]     + g_m2p[114688 + i];
    float v = (s01 + s23) + (s45 + s67);
    int row = 496 + (i >> 7), c = i & 127;
    *(float2*)&g_Bd[(size_t)row * 256 + dup_fpos(c)] = make_float2(v, v);
}

// ============================================================
// Fused kernel: score phase + in-CTA split-K GEMM (2 x 128-thread
// groups, dup-B zero-pack inner loop) + 2-way parallel epilogue.
// ============================================================
#define KV_CC_STRIDE 11664           // 324*36 floats
#define SMEM_SCORE ((4*KV_CC_STRIDE + 64*132) * 4)

typedef unsigned long long ull;
__device__ __forceinline__ ull pk2(float x, float y) {
    ull r;
    asm("mov.b64 %0, {%1,%2};" : "=l"(r) : "f"(x), "f"(y));
    return r;
}
__device__ __forceinline__ void fma2(ull& d, ull a, ull b) {
    asm("fma.rn.f32x2 %0, %1, %2, %3;" : "=l"(d) : "l"(a), "l"(b), "l"(d));
}
__device__ __forceinline__ void upk2(ull v, float& x, float& y) {
    asm("mov.b64 {%0,%1}, %2;" : "=f"(x), "=f"(y) : "l"(v));
}
#define GBAR(id) asm volatile("bar.sync %0, 128;" :: "r"(id) : "memory")

// GEMM-phase smem overlay (floats):
//  [0)      G0: As 2*16*64 (2048) + Bs 2*16*256 (8192) = 10240
//  [10240)  G1: As + Bs
//  [20480)  pub0: G0's mm4..7 partials, 128 slots * 34
//  [24832)  pub1: G1's mm0..3 partials
#define GRP_STRIDE 10240
#define PUB_OFF 20480
#define PUB_STRIDE 4352   // 34*128

// Publish 4 mm-columns starting at compile-time PUBBASE.
// acc[mp][nl]: pair (m = ty*8 + 2*mp + {lo,hi}), nl = 0..7 (n0+0..3, n1+0..3)
template<int PUBBASE>
__device__ __forceinline__ void publish4(ull (&acc)[4][8], float* pub, int lt) {
    #pragma unroll
    for (int mmi = 0; mmi < 4; mmi++) {
        const int mm = PUBBASE + mmi;
        #pragma unroll
        for (int nl = 0; nl < 8; nl++) {
            float lo, hi;
            upk2(acc[mm >> 1][nl], lo, hi);
            pub[lt * 34 + mmi * 8 + nl] = (mm & 1) ? hi : lo;
        }
    }
}

// Epilogue for 4 mm-columns starting at compile-time MYBASE.
template<int MYBASE>
__device__ __forceinline__ void epilogue4(
    ull (&acc)[4][8], const float* pubo,
    const float* __restrict__ q, const float* __restrict__ bias,
    const float* __restrict__ lng, const float* __restrict__ lnb,
    float* __restrict__ out,
    int b, int h0, int w0, int ty, int lt, int n0, int n1) {
    float bi[8], gg[8], bb[8];
    {
        float4 t0 = *(const float4*)&bias[n0];
        float4 t1 = *(const float4*)&bias[n1];
        bi[0] = t0.x; bi[1] = t0.y; bi[2] = t0.z; bi[3] = t0.w;
        bi[4] = t1.x; bi[5] = t1.y; bi[6] = t1.z; bi[7] = t1.w;
        t0 = *(const float4*)&lng[n0]; t1 = *(const float4*)&lng[n1];
        gg[0] = t0.x; gg[1] = t0.y; gg[2] = t0.z; gg[3] = t0.w;
        gg[4] = t1.x; gg[5] = t1.y; gg[6] = t1.z; gg[7] = t1.w;
        t0 = *(const float4*)&lnb[n0]; t1 = *(const float4*)&lnb[n1];
        bb[0] = t0.x; bb[1] = t0.y; bb[2] = t0.z; bb[3] = t0.w;
        bb[4] = t1.x; bb[5] = t1.y; bb[6] = t1.z; bb[7] = t1.w;
    }
    const float inv128 = 1.0f / 128.0f;
    const float rsqrt2 = 0.70710678118654752f;

    #pragma unroll
    for (int mmi = 0; mmi < 4; mmi++) {
        const int mm = MYBASE + mmi;       // compile-time after unroll
        int pixg = (b * HH + h0 + ty) * WW + w0 + mm;
        float4 q0 = *(const float4*)&q[(size_t)pixg * CCH + n0];
        float4 q1 = *(const float4*)&q[(size_t)pixg * CCH + n1];
        float qv[8] = {q0.x, q0.y, q0.z, q0.w, q1.x, q1.y, q1.z, q1.w};
        float x[8];
        float s1 = 0.f, s2 = 0.f;
        #pragma unroll
        for (int n2 = 0; n2 < 4; n2++) {
            float lo0, hi0, lo1, hi1;
            upk2(acc[mm >> 1][2 * n2 + 0], lo0, hi0);
            upk2(acc[mm >> 1][2 * n2 + 1], lo1, hi1);
            float a0 = (mm & 1) ? hi0 : lo0;
            float a1 = (mm & 1) ? hi1 : lo1;
            float2 pp = *(const float2*)&pubo[lt * 34 + mmi * 8 + n2 * 2];
            float p0 = a0 + pp.x + bi[n2 * 2 + 0];
            float p1 = a1 + pp.y + bi[n2 * 2 + 1];
            float e0 = 0.5f * p0 * (1.f + erff(p0 * rsqrt2));
            float e1 = 0.5f * p1 * (1.f + erff(p1 * rsqrt2));
            float x0 = e0 + qv[n2 * 2 + 0];
            float x1 = e1 + qv[n2 * 2 + 1];
            x[n2 * 2 + 0] = x0; x[n2 * 2 + 1] = x1;
            s1 += x0 + x1;
            s2 += x0 * x0 + x1 * x1;
        }
        #pragma unroll
        for (int ofs = 8; ofs >= 1; ofs >>= 1) {
            s1 += __shfl_xor_sync(0xffffffffu, s1, ofs);
            s2 += __shfl_xor_sync(0xffffffffu, s2, ofs);
        }
        float mean = s1 * inv128;
        float var = s2 * inv128 - mean * mean;
        float rstd = rsqrtf(var + 1e-5f);
        *(float4*)&out[(size_t)pixg * CCH + n0] = make_float4(
            (x[0] - mean) * rstd * gg[0] + bb[0],
            (x[1] - mean) * rstd * gg[1] + bb[1],
            (x[2] - mean) * rstd * gg[2] + bb[2],
            (x[3] - mean) * rstd * gg[3] + bb[3]);
        *(float4*)&out[(size_t)pixg * CCH + n1] = make_float4(
            (x[4] - mean) * rstd * gg[4] + bb[4],
            (x[5] - mean) * rstd * gg[5] + bb[5],
            (x[6] - mean) * rstd * gg[6] + bb[6],
            (x[7] - mean) * rstd * gg[7] + bb[7]);
    }
}

__global__ __launch_bounds__(256, 1) void fused_kernel(
    const float* __restrict__ q,
    const float* __restrict__ kv,
    const float* __restrict__ bias,
    const float* __restrict__ lng,
    const float* __restrict__ lnb,
    float* __restrict__ out) {
    extern __shared__ float smem[];
    float* s_kv = smem;
    float* s_q  = smem + 4 * KV_CC_STRIDE;

    const int tid = threadIdx.x;
    const int b = blockIdx.z, h0 = blockIdx.y * 8, w0 = blockIdx.x * 8;

    // ================= STAGING =================
    for (int idx = tid; idx < 324 * 32; idx += 256) {
        int pos = idx >> 5, c4 = idx & 31;
        int r = pos / 18, xc = pos - r * 18;
        int y = h0 - 5 + r, x = w0 - 5 + xc;
        float4 v = make_float4(0.f, 0.f, 0.f, 0.f);
        if ((unsigned)y < HH && (unsigned)x < WW)
            v = ((const float4*)(kv + (size_t)((b * HH + y) * WW + x) * CCH))[c4];
        int cc = c4 >> 3, d4 = c4 & 7;
        *(float4*)&s_kv[cc * KV_CC_STRIDE + pos * 36 + d4 * 4] = v;
    }
    for (int idx = tid; idx < 64 * 32; idx += 256) {
        int px = idx >> 5, c4 = idx & 31;
        int ph = px >> 3, pw = px & 7;
        int pixg = (b * HH + h0 + ph) * WW + (w0 + pw);
        float4 v = ((const float4*)(q + (size_t)pixg * CCH))[c4];
        *(float4*)&s_q[px * 132 + c4 * 4] = v;
        *(float4*)&g_A[(size_t)pixg * KA + 496 + c4 * 4] = v;
    }
    __syncthreads();

    // ================= SCORE PHASE (quads, R8-proven compute) =================
    {
        const int dg   = tid & 3;
        const int cc   = (tid >> 2) & 3;
        const int quad = tid >> 4;                  // 0..15
        const int qrow = quad >> 1, qcol = quad & 1;
        const int pxb  = qrow * 8 + qcol * 4;
        const int pixg0 = (b * HH + h0 + qrow) * WW + (w0 + qcol * 4);
        const float* ccb = s_kv + cc * KV_CC_STRIDE;
        const bool dlow = (dg & 2) == 0;
        const bool deven = (dg & 1) == 0;

        #pragma unroll 1
        for (int i = 0; i < 11; i++) {
            float acc[4][11];
            #pragma unroll
            for (int k = 0; k < 4; k++)
                #pragma unroll
                for (int j = 0; j < 11; j++) acc[k][j] = 0.f;

            int gA = (44 * i) / 121;
            bool cross = (i == 2) | (i == 5) | (i == 8);
            int sbase = 44 * i + cc;
            int thr2 = 121 * (gA + 1);

            #pragma unroll 1
            for (int hd = 0; hd < 2; hd++) {
                int d4 = dg + 4 * hd;
                float4 qA[4];
                #pragma unroll
                for (int k = 0; k < 4; k++)
                    qA[k] = *(const float4*)&s_q[(pxb + k) * 132 + gA * 32 + d4 * 4];
                float4 win[14];
                const float* rowp = ccb + ((qrow + i) * 18 + qcol * 4) * 36 + d4 * 4;
                #pragma unroll
                for (int x = 0; x < 14; x++) win[x] = *(const float4*)&rowp[x * 36];

                if (!cross) {
                    #pragma unroll
                    for (int j = 0; j < 11; j++) {
                        #pragma unroll
                        for (int k = 0; k < 4; k++) {
                            float4 kvv = win[j + k];
                            acc[k][j] += kvv.x * qA[k].x + kvv.y * qA[k].y
                                       + kvv.z * qA[k].z + kvv.w * qA[k].w;
                        }
                    }
                } else {
                    float4 qB[4];
                    #pragma unroll
                    for (int k = 0; k < 4; k++)
                        qB[k] = *(const float4*)&s_q[(pxb + k) * 132 + (gA + 1) * 32 + d4 * 4];
                    #pragma unroll
                    for (int j = 0; j < 11; j++) {
                        bool sel = (sbase + 4 * j) >= thr2;
                        #pragma unroll
                        for (int k = 0; k < 4; k++) {
                            float4 qv = sel ? qB[k] : qA[k];
                            float4 kvv = win[j + k];
                            acc[k][j] += kvv.x * qv.x + kvv.y * qv.y
                                       + kvv.z * qv.z + kvv.w * qv.w;
                        }
                    }
                }
            }

            // ---- reducing transpose across dg lanes: lane dg ends with k=dg ----
            float k0[11], k1[11];
            #pragma unroll
            for (int j = 0; j < 11; j++) {
                float s0 = dlow ? acc[2][j] : acc[0][j];
                float s1 = dlow ? acc[3][j] : acc[1][j];
                float r0 = __shfl_xor_sync(0xffffffffu, s0, 2);
                float r1 = __shfl_xor_sync(0xffffffffu, s1, 2);
                k0[j] = (dlow ? acc[0][j] : acc[2][j]) + r0;
                k1[j] = (dlow ? acc[1][j] : acc[3][j]) + r1;
            }
            float* outp = g_A + (size_t)(pixg0 + dg) * KA + cc * 124 + 11 * i;
            #pragma unroll
            for (int j = 0; j < 11; j++) {
                float s = deven ? k1[j] : k0[j];
                float r = __shfl_xor_sync(0xffffffffu, s, 1);
                outp[j] = (deven ? k0[j] : k1[j]) + r;
            }
        }
    }
    __syncthreads();   // scores + q mirror in g_A visible; smem free

    // ================= GEMM PHASE (two 128-thread split-K groups) =================
    const int g  = tid >> 7;          // group 0/1
    const int lt = tid & 127;
    const int tx = lt & 15, ty = lt >> 4;
    const int n0 = tx * 4, n1 = 64 + tx * 4;
    const int pixL = lt >> 1, halfk = (lt & 1) * 8;
    const int brow8 = lt >> 3, bc8 = lt & 7;    // B staging: row (0..15), col base
    const int kbeg = g ? 320 : 0;
    const int nk   = g ? 19 : 20;     // 320 + 304 = 624
    const int barid = 1 + g;

    float* as_ = smem + g * GRP_STRIDE;            // [2][16][64]
    float* bs_ = smem + g * GRP_STRIDE + 2048;     // [2][16][256]

    const float* Arow = g_A + (size_t)((b * HH + h0 + (pixL >> 3)) * WW + w0 + (pixL & 7)) * KA + kbeg;

    ull acc[4][8];
    #pragma unroll
    for (int m = 0; m < 4; m++)
        #pragma unroll
        for (int n = 0; n < 8; n++) acc[m][n] = 0ULL;

    float4 av0 = *(const float4*)&Arow[halfk];
    float4 av1 = *(const float4*)&Arow[halfk + 4];
    float4 bv[8];
    #pragma unroll
    for (int r = 0; r < 8; r++)
        bv[r] = *(const float4*)&g_Bd[(size_t)(kbeg + brow8) * 256 + (bc8 + 8 * r) * 4];

    int buf = 0;
    as_[(halfk + 0) * 64 + pixL] = av0.x;
    as_[(halfk + 1) * 64 + pixL] = av0.y;
    as_[(halfk + 2) * 64 + pixL] = av0.z;
    as_[(halfk + 3) * 64 + pixL] = av0.w;
    as_[(halfk + 4) * 64 + pixL] = av1.x;
    as_[(halfk + 5) * 64 + pixL] = av1.y;
    as_[(halfk + 6) * 64 + pixL] = av1.z;
    as_[(halfk + 7) * 64 + pixL] = av1.w;
    #pragma unroll
    for (int r = 0; r < 8; r++)
        *(float4*)&bs_[brow8 * 256 + (bc8 + 8 * r) * 4] = bv[r];
    GBAR(barid);

    for (int kc = 0; kc < nk; kc++) {
        bool more = (kc + 1 < nk);
        if (more) {
            int kn = (kc + 1) * GK;
            av0 = *(const float4*)&Arow[kn + halfk];
            av1 = *(const float4*)&Arow[kn + halfk + 4];
            #pragma unroll
            for (int r = 0; r < 8; r++)
                bv[r] = *(const float4*)&g_Bd[(size_t)(kbeg + kn + brow8) * 256 + (bc8 + 8 * r) * 4];
        }
        const float* asb = as_ + buf * 1024;
        const float* bsb = bs_ + buf * 4096;
        #pragma unroll
        for (int k = 0; k < GK; k++) {
            ulonglong2 aq0 = *(const ulonglong2*)&asb[k * 64 + ty * 8];
            ulonglong2 aq1 = *(const ulonglong2*)&asb[k * 64 + ty * 8 + 4];
            ulonglong2 b0 = *(const ulonglong2*)&bsb[k * 256 + (0 * 16 + tx) * 4];
            ulonglong2 b1 = *(const ulonglong2*)&bsb[k * 256 + (1 * 16 + tx) * 4];
            ulonglong2 b2 = *(const ulonglong2*)&bsb[k * 256 + (2 * 16 + tx) * 4];
            ulonglong2 b3 = *(const ulonglong2*)&bsb[k * 256 + (3 * 16 + tx) * 4];
            ull ap[4] = {aq0.x, aq0.y, aq1.x, aq1.y};
            ull bd[8] = {b0.x, b0.y, b1.x, b1.y, b2.x, b2.y, b3.x, b3.y};
            #pragma unroll
            for (int mp = 0; mp < 4; mp++)
                #pragma unroll
                for (int nl = 0; nl < 8; nl++)
                    fma2(acc[mp][nl], ap[mp], bd[nl]);
        }
        if (more) {
            int nb = buf ^ 1;
            float* asn = as_ + nb * 1024;
            float* bsn = bs_ + nb * 4096;
            asn[(halfk + 0) * 64 + pixL] = av0.x;
            asn[(halfk + 1) * 64 + pixL] = av0.y;
            asn[(halfk + 2) * 64 + pixL] = av0.z;
            asn[(halfk + 3) * 64 + pixL] = av0.w;
            asn[(halfk + 4) * 64 + pixL] = av1.x;
            asn[(halfk + 5) * 64 + pixL] = av1.y;
            asn[(halfk + 6) * 64 + pixL] = av1.z;
            asn[(halfk + 7) * 64 + pixL] = av1.w;
            #pragma unroll
            for (int r = 0; r < 8; r++)
                *(float4*)&bsn[brow8 * 256 + (bc8 + 8 * r) * 4] = bv[r];
            GBAR(barid);
            buf = nb;
        }
    }

    // ---- publish (compile-time indices): G0 -> mm4..7, G1 -> mm0..3 ----
    if (g == 0) publish4<4>(acc, smem + PUB_OFF,              lt);
    else        publish4<0>(acc, smem + PUB_OFF + PUB_STRIDE, lt);
    __syncthreads();

    // ---- epilogue (compile-time indices): G0 -> mm0..3, G1 -> mm4..7 ----
    if (g == 0)
        epilogue4<0>(acc, smem + PUB_OFF + PUB_STRIDE, q, bias, lng, lnb, out,
                     b, h0, w0, ty, lt, n0, n1);
    else
        epilogue4<4>(acc, smem + PUB_OFF,              q, bias, lng, lnb, out,
                     b, h0, w0, ty, lt, n0, n1);
}

// ============================================================
extern "C" void kernel_launch(void* const* d_in, const int* in_sizes, int n_in,
                              void* d_out, int out_size) {
    const float* q    = (const float*)d_in[0];
    const float* kv   = (const float*)d_in[1];
    const float* pos  = (const float*)d_in[2];
    const float* W    = (const float*)d_in[3];
    const float* bias = (const float*)d_in[4];
    const float* lng  = (const float*)d_in[5];
    const float* lnb  = (const float*)d_in[6];
    float* out = (float*)d_out;

    static int smem_set = 0;
    if (!smem_set) {
        cudaFuncSetAttribute(fused_kernel,
                             cudaFuncAttributeMaxDynamicSharedMemorySize, SMEM_SCORE);
        smem_set = 1;
    }

    prep_permute<<<248, 256>>>(W);
    prep_m2_partial<<<dim3(8, CCH), 128>>>(W, pos);
    prep_m2_combine<<<64, 256>>>();
    fused_kernel<<<dim3(WW / 8, HH / 8, BATCH), 256, SMEM_SCORE>>>(q, kv, bias, lng, lnb, out);
}

// round 16
// speedup vs baseline: 1.1236x; 1.1236x over previous
#include <cuda_runtime.h>
#include <math.h>

#define HH 64
#define WW 64
#define BATCH 2
#define CCH 128
#define NPIX (BATCH*HH*WW)
#define KA 624   // unified K: 496 score cols (4cc x 124) + 128 q cols
#define GK 16    // GEMM K-chunk

// ---- scratch ----
__device__ float g_A[(size_t)NPIX * KA];   // [pixel][0..495: scores, 496..623: q]
__device__ float g_B[KA * CCH];            // rows 0..495: wperm, 496..623: m2
__device__ float g_m2p[8 * CCH * CCH];     // split-K partials (8-way)

// ============================================================
// Prep A: permute W rows (s=4p+cc -> s'=cc*124+p) into g_B[0..495].
// ============================================================
__global__ __launch_bounds__(256) void prep_permute(const float* __restrict__ W) {
    int gid = blockIdx.x * 256 + threadIdx.x;     // 0..15871
    int row = gid >> 5, c4 = gid & 31;
    int cc = row / 124, p = row - cc * 124;
    float4 v = make_float4(0.f, 0.f, 0.f, 0.f);
    if (p < 121) v = ((const float4*)(W + (size_t)(4 * p + cc) * CCH))[c4];
    ((float4*)(g_B + (size_t)row * CCH))[c4] = v;
}

// ============================================================
// Prep B: M2 partials (8-way split-K) + combine into g_B rows 496..623.
// ============================================================
__global__ __launch_bounds__(128) void prep_m2_partial(const float* __restrict__ W,
                                                       const float* __restrict__ pos) {
    int o = threadIdx.x;
    int ks = blockIdx.x, c = blockIdx.y;       // grid (8, 128)
    int g = c >> 5, cm = c & 31;
    int s0 = 121 * g;
    int pbeg = ks * 16;
    int pend = (pbeg + 16 < 121) ? pbeg + 16 : 121;

    float a0 = 0.f, a1 = 0.f, a2 = 0.f, a3 = 0.f;
    int p = pbeg;
    for (; p + 4 <= pend; p += 4) {
        a0 += pos[(s0 + p + 0) * 32 + cm] * W[(size_t)(s0 + p + 0) * CCH + o];
        a1 += pos[(s0 + p + 1) * 32 + cm] * W[(size_t)(s0 + p + 1) * CCH + o];
        a2 += pos[(s0 + p + 2) * 32 + cm] * W[(size_t)(s0 + p + 2) * CCH + o];
        a3 += pos[(s0 + p + 3) * 32 + cm] * W[(size_t)(s0 + p + 3) * CCH + o];
    }
    for (; p < pend; p++)
        a0 += pos[(s0 + p) * 32 + cm] * W[(size_t)(s0 + p) * CCH + o];
    g_m2p[((size_t)ks * CCH + c) * CCH + o] = (a0 + a1) + (a2 + a3);
}

__global__ __launch_bounds__(256) void prep_m2_combine() {
    int i = blockIdx.x * 256 + threadIdx.x;       // 0..16383
    float s01 = g_m2p[i]             + g_m2p[16384 + i];
    float s23 = g_m2p[32768 + i]     + g_m2p[49152 + i];
    float s45 = g_m2p[65536 + i]     + g_m2p[81920 + i];
    float s67 = g_m2p[98304 + i]     + g_m2p[114688 + i];
    g_B[496 * CCH + i] = (s01 + s23) + (s45 + s67);
}

// ============================================================
// Fused kernel: score phase + in-CTA split-K GEMM (2 x 128-thread
// groups, A DUPLICATED IN SMEM -> zero-pack inner loop) + 2-way
// parallel epilogue with compile-time acc indexing.
// ============================================================
#define KV_CC_STRIDE 11664           // 324*36 floats
#define SMEM_SCORE ((4*KV_CC_STRIDE + 64*132) * 4)

typedef unsigned long long ull;
__device__ __forceinline__ void fma2(ull& d, ull a, ull b) {
    asm("fma.rn.f32x2 %0, %1, %2, %3;" : "=l"(d) : "l"(a), "l"(b), "l"(d));
}
__device__ __forceinline__ void upk2(ull v, float& x, float& y) {
    asm("mov.b64 {%0,%1}, %2;" : "=f"(x), "=f"(y) : "l"(v));
}
#define GBAR(id) asm volatile("bar.sync %0, 128;" :: "r"(id) : "memory")

// GEMM-phase smem overlay (floats):
//  [0)      G0: As-dup 2 buf * 16 * 128 (4096) + Bs 2 * 16 * 128 (4096)
//  [8192)   G1: As-dup + Bs
//  [16384)  pub0: G0's mm4..7 partials, 128 slots * 34
//  [20736)  pub1: G1's mm0..3 partials
#define GRP_STRIDE 8192
#define PUB_OFF 16384
#define PUB_STRIDE 4352   // 34*128

// Publish 4 mm-columns starting at compile-time PUBBASE (constant reg indices).
template<int PUBBASE>
__device__ __forceinline__ void publish4(ull (&acc)[8][4], float* pub, int lt) {
    #pragma unroll
    for (int mmi = 0; mmi < 4; mmi++)
        #pragma unroll
        for (int n = 0; n < 4; n++)
            *(ull*)&pub[lt * 34 + mmi * 8 + n * 2] = acc[PUBBASE + mmi][n];
}

// Epilogue for 4 mm-columns starting at compile-time MYBASE.
template<int MYBASE>
__device__ __forceinline__ void epilogue4(
    ull (&acc)[8][4], const float* pubo,
    const float* __restrict__ q, const float* __restrict__ bias,
    const float* __restrict__ lng, const float* __restrict__ lnb,
    float* __restrict__ out,
    int b, int h0, int w0, int ty, int lt, int n0, int n1) {
    float bi[8], gg[8], bb[8];
    {
        float4 t0 = *(const float4*)&bias[n0];
        float4 t1 = *(const float4*)&bias[n1];
        bi[0] = t0.x; bi[1] = t0.y; bi[2] = t0.z; bi[3] = t0.w;
        bi[4] = t1.x; bi[5] = t1.y; bi[6] = t1.z; bi[7] = t1.w;
        t0 = *(const float4*)&lng[n0]; t1 = *(const float4*)&lng[n1];
        gg[0] = t0.x; gg[1] = t0.y; gg[2] = t0.z; gg[3] = t0.w;
        gg[4] = t1.x; gg[5] = t1.y; gg[6] = t1.z; gg[7] = t1.w;
        t0 = *(const float4*)&lnb[n0]; t1 = *(const float4*)&lnb[n1];
        bb[0] = t0.x; bb[1] = t0.y; bb[2] = t0.z; bb[3] = t0.w;
        bb[4] = t1.x; bb[5] = t1.y; bb[6] = t1.z; bb[7] = t1.w;
    }
    const float inv128 = 1.0f / 128.0f;
    const float rsqrt2 = 0.70710678118654752f;

    #pragma unroll
    for (int mmi = 0; mmi < 4; mmi++) {
        const int mm = MYBASE + mmi;       // compile-time after unroll
        int pixg = (b * HH + h0 + ty) * WW + w0 + mm;
        float4 q0 = *(const float4*)&q[(size_t)pixg * CCH + n0];
        float4 q1 = *(const float4*)&q[(size_t)pixg * CCH + n1];
        float qv[8] = {q0.x, q0.y, q0.z, q0.w, q1.x, q1.y, q1.z, q1.w};
        float x[8];
        float s1 = 0.f, s2 = 0.f;
        #pragma unroll
        for (int n2 = 0; n2 < 4; n2++) {
            float lo, hi;
            upk2(acc[mm][n2], lo, hi);
            float2 pp = *(const float2*)&pubo[lt * 34 + mmi * 8 + n2 * 2];
            float p0 = lo + pp.x + bi[n2 * 2 + 0];
            float p1 = hi + pp.y + bi[n2 * 2 + 1];
            float e0 = 0.5f * p0 * (1.f + erff(p0 * rsqrt2));
            float e1 = 0.5f * p1 * (1.f + erff(p1 * rsqrt2));
            float x0 = e0 + qv[n2 * 2 + 0];
            float x1 = e1 + qv[n2 * 2 + 1];
            x[n2 * 2 + 0] = x0; x[n2 * 2 + 1] = x1;
            s1 += x0 + x1;
            s2 += x0 * x0 + x1 * x1;
        }
        #pragma unroll
        for (int ofs = 8; ofs >= 1; ofs >>= 1) {
            s1 += __shfl_xor_sync(0xffffffffu, s1, ofs);
            s2 += __shfl_xor_sync(0xffffffffu, s2, ofs);
        }
        float mean = s1 * inv128;
        float var = s2 * inv128 - mean * mean;
        float rstd = rsqrtf(var + 1e-5f);
        *(float4*)&out[(size_t)pixg * CCH + n0] = make_float4(
            (x[0] - mean) * rstd * gg[0] + bb[0],
            (x[1] - mean) * rstd * gg[1] + bb[1],
            (x[2] - mean) * rstd * gg[2] + bb[2],
            (x[3] - mean) * rstd * gg[3] + bb[3]);
        *(float4*)&out[(size_t)pixg * CCH + n1] = make_float4(
            (x[4] - mean) * rstd * gg[4] + bb[4],
            (x[5] - mean) * rstd * gg[5] + bb[5],
            (x[6] - mean) * rstd * gg[6] + bb[6],
            (x[7] - mean) * rstd * gg[7] + bb[7]);
    }
}

__global__ __launch_bounds__(256, 1) void fused_kernel(
    const float* __restrict__ q,
    const float* __restrict__ kv,
    const float* __restrict__ bias,
    const float* __restrict__ lng,
    const float* __restrict__ lnb,
    float* __restrict__ out) {
    extern __shared__ float smem[];
    float* s_kv = smem;
    float* s_q  = smem + 4 * KV_CC_STRIDE;

    const int tid = threadIdx.x;
    const int b = blockIdx.z, h0 = blockIdx.y * 8, w0 = blockIdx.x * 8;

    // ================= STAGING =================
    for (int idx = tid; idx < 324 * 32; idx += 256) {
        int pos = idx >> 5, c4 = idx & 31;
        int r = pos / 18, xc = pos - r * 18;
        int y = h0 - 5 + r, x = w0 - 5 + xc;
        float4 v = make_float4(0.f, 0.f, 0.f, 0.f);
        if ((unsigned)y < HH && (unsigned)x < WW)
            v = ((const float4*)(kv + (size_t)((b * HH + y) * WW + x) * CCH))[c4];
        int cc = c4 >> 3, d4 = c4 & 7;
        *(float4*)&s_kv[cc * KV_CC_STRIDE + pos * 36 + d4 * 4] = v;
    }
    for (int idx = tid; idx < 64 * 32; idx += 256) {
        int px = idx >> 5, c4 = idx & 31;
        int ph = px >> 3, pw = px & 7;
        int pixg = (b * HH + h0 + ph) * WW + (w0 + pw);
        float4 v = ((const float4*)(q + (size_t)pixg * CCH))[c4];
        *(float4*)&s_q[px * 132 + c4 * 4] = v;
        *(float4*)&g_A[(size_t)pixg * KA + 496 + c4 * 4] = v;
    }
    __syncthreads();

    // ================= SCORE PHASE (quads, R8-proven) =================
    {
        const int dg   = tid & 3;
        const int cc   = (tid >> 2) & 3;
        const int quad = tid >> 4;                  // 0..15
        const int qrow = quad >> 1, qcol = quad & 1;
        const int pxb  = qrow * 8 + qcol * 4;
        const int pixg0 = (b * HH + h0 + qrow) * WW + (w0 + qcol * 4);
        const float* ccb = s_kv + cc * KV_CC_STRIDE;

        #pragma unroll 1
        for (int i = 0; i < 11; i++) {
            float acc[4][11];
            #pragma unroll
            for (int k = 0; k < 4; k++)
                #pragma unroll
                for (int j = 0; j < 11; j++) acc[k][j] = 0.f;

            int gA = (44 * i) / 121;
            bool cross = (i == 2) | (i == 5) | (i == 8);
            int sbase = 44 * i + cc;
            int thr2 = 121 * (gA + 1);

            #pragma unroll 1
            for (int hd = 0; hd < 2; hd++) {
                int d4 = dg + 4 * hd;
                float4 qA[4];
                #pragma unroll
                for (int k = 0; k < 4; k++)
                    qA[k] = *(const float4*)&s_q[(pxb + k) * 132 + gA * 32 + d4 * 4];
                float4 win[14];
                const float* rowp = ccb + ((qrow + i) * 18 + qcol * 4) * 36 + d4 * 4;
                #pragma unroll
                for (int x = 0; x < 14; x++) win[x] = *(const float4*)&rowp[x * 36];

                if (!cross) {
                    #pragma unroll
                    for (int j = 0; j < 11; j++) {
                        #pragma unroll
                        for (int k = 0; k < 4; k++) {
                            float4 kvv = win[j + k];
                            acc[k][j] += kvv.x * qA[k].x + kvv.y * qA[k].y
                                       + kvv.z * qA[k].z + kvv.w * qA[k].w;
                        }
                    }
                } else {
                    float4 qB[4];
                    #pragma unroll
                    for (int k = 0; k < 4; k++)
                        qB[k] = *(const float4*)&s_q[(pxb + k) * 132 + (gA + 1) * 32 + d4 * 4];
                    #pragma unroll
                    for (int j = 0; j < 11; j++) {
                        bool sel = (sbase + 4 * j) >= thr2;
                        #pragma unroll
                        for (int k = 0; k < 4; k++) {
                            float4 qv = sel ? qB[k] : qA[k];
                            float4 kvv = win[j + k];
                            acc[k][j] += kvv.x * qv.x + kvv.y * qv.y
                                       + kvv.z * qv.z + kvv.w * qv.w;
                        }
                    }
                }
            }

            #pragma unroll
            for (int k = 0; k < 4; k++) {
                float* outp = g_A + (size_t)(pixg0 + k) * KA + cc * 124 + 11 * i;
                #pragma unroll
                for (int j = 0; j < 11; j++) {
                    float v = acc[k][j];
                    v += __shfl_xor_sync(0xffffffffu, v, 1);
                    v += __shfl_xor_sync(0xffffffffu, v, 2);
                    if (dg == 0) outp[j] = v;
                }
            }
        }
    }
    __syncthreads();   // scores + q mirror in g_A visible; smem free

    // ================= GEMM PHASE (two 128-thread split-K groups) =================
    const int g  = tid >> 7;          // group 0/1
    const int lt = tid & 127;
    const int tx = lt & 15, ty = lt >> 4;
    const int n0 = tx * 4, n1 = 64 + tx * 4;
    const int pixL = lt >> 1, halfk = (lt & 1) * 8;
    const int brow = lt >> 5, bcol = (lt & 31) * 4;
    const int kbeg = g ? 320 : 0;
    const int nk   = g ? 19 : 20;     // 320 + 304 = 624
    const int barid = 1 + g;

    float* as_ = smem + g * GRP_STRIDE;            // A-dup: [2][16][128]
    float* bs_ = smem + g * GRP_STRIDE + 4096;     // [2][16][128]

    const float* Arow = g_A + (size_t)((b * HH + h0 + (pixL >> 3)) * WW + w0 + (pixL & 7)) * KA + kbeg;
    const float* B = g_B + (size_t)kbeg * CCH;

    ull acc[8][4];
    #pragma unroll
    for (int m = 0; m < 8; m++)
        #pragma unroll
        for (int n = 0; n < 4; n++) acc[m][n] = 0ULL;

    float4 av0 = *(const float4*)&Arow[halfk];
    float4 av1 = *(const float4*)&Arow[halfk + 4];
    float4 bv[4];
    #pragma unroll
    for (int r = 0; r < 4; r++)
        bv[r] = *(const float4*)&B[(size_t)(brow + 4 * r) * CCH + bcol];

    int buf = 0;
    {
        float a8[8] = {av0.x, av0.y, av0.z, av0.w, av1.x, av1.y, av1.z, av1.w};
        #pragma unroll
        for (int jj = 0; jj < 8; jj++)
            *(float2*)&as_[(halfk + jj) * 128 + 2 * pixL] = make_float2(a8[jj], a8[jj]);
    }
    #pragma unroll
    for (int r = 0; r < 4; r++)
        *(float4*)&bs_[(brow + 4 * r) * 128 + bcol] = bv[r];
    GBAR(barid);

    for (int kc = 0; kc < nk; kc++) {
        bool more = (kc + 1 < nk);
        if (more) {
            int kn = (kc + 1) * GK;
            av0 = *(const float4*)&Arow[kn + halfk];
            av1 = *(const float4*)&Arow[kn + halfk + 4];
            #pragma unroll
            for (int r = 0; r < 4; r++)
                bv[r] = *(const float4*)&B[(size_t)(kn + brow + 4 * r) * CCH + bcol];
        }
        const float* asb = as_ + buf * 2048;
        const float* bsb = bs_ + buf * 2048;
        #pragma unroll
        for (int k = 0; k < GK; k++) {
            ulonglong2 aq0 = *(const ulonglong2*)&asb[k * 128 + ty * 16];
            ulonglong2 aq1 = *(const ulonglong2*)&asb[k * 128 + ty * 16 + 4];
            ulonglong2 aq2 = *(const ulonglong2*)&asb[k * 128 + ty * 16 + 8];
            ulonglong2 aq3 = *(const ulonglong2*)&asb[k * 128 + ty * 16 + 12];
            ulonglong2 bq0 = *(const ulonglong2*)&bsb[k * 128 + n0];
            ulonglong2 bq1 = *(const ulonglong2*)&bsb[k * 128 + n1];
            ull ad[8] = {aq0.x, aq0.y, aq1.x, aq1.y, aq2.x, aq2.y, aq3.x, aq3.y};
            ull bp[4] = {bq0.x, bq0.y, bq1.x, bq1.y};
            #pragma unroll
            for (int m = 0; m < 8; m++)
                #pragma unroll
                for (int n = 0; n < 4; n++) fma2(acc[m][n], ad[m], bp[n]);
        }
        if (more) {
            int nb = buf ^ 1;
            float* asn = as_ + nb * 2048;
            float* bsn = bs_ + nb * 2048;
            float a8[8] = {av0.x, av0.y, av0.z, av0.w, av1.x, av1.y, av1.z, av1.w};
            #pragma unroll
            for (int jj = 0; jj < 8; jj++)
                *(float2*)&asn[(halfk + jj) * 128 + 2 * pixL] = make_float2(a8[jj], a8[jj]);
            #pragma unroll
            for (int r = 0; r < 4; r++)
                *(float4*)&bsn[(brow + 4 * r) * 128 + bcol] = bv[r];
            GBAR(barid);
            buf = nb;
        }
    }

    // ---- publish (compile-time indices): G0 -> mm4..7, G1 -> mm0..3 ----
    if (g == 0) publish4<4>(acc, smem + PUB_OFF,              lt);
    else        publish4<0>(acc, smem + PUB_OFF + PUB_STRIDE, lt);
    __syncthreads();

    // ---- epilogue (compile-time indices): G0 -> mm0..3, G1 -> mm4..7 ----
    if (g == 0)
        epilogue4<0>(acc, smem + PUB_OFF + PUB_STRIDE, q, bias, lng, lnb, out,
                     b, h0, w0, ty, lt, n0, n1);
    else
        epilogue4<4>(acc, smem + PUB_OFF,              q, bias, lng, lnb, out,
                     b, h0, w0, ty, lt, n0, n1);
}

// ============================================================
extern "C" void kernel_launch(void* const* d_in, const int* in_sizes, int n_in,
                              void* d_out, int out_size) {
    const float* q    = (const float*)d_in[0];
    const float* kv   = (const float*)d_in[1];
    const float* pos  = (const float*)d_in[2];
    const float* W    = (const float*)d_in[3];
    const float* bias = (const float*)d_in[4];
    const float* lng  = (const float*)d_in[5];
    const float* lnb  = (const float*)d_in[6];
    float* out = (float*)d_out;

    static int smem_set = 0;
    if (!smem_set) {
        cudaFuncSetAttribute(fused_kernel,
                             cudaFuncAttributeMaxDynamicSharedMemorySize, SMEM_SCORE);
        smem_set = 1;
    }

    prep_permute<<<62, 256>>>(W);
    prep_m2_partial<<<dim3(8, CCH), 128>>>(W, pos);
    prep_m2_combine<<<64, 256>>>();
    fused_kernel<<<dim3(WW / 8, HH / 8, BATCH), 256, SMEM_SCORE>>>(q, kv, bias, lng, lnb, out);
}

// round 17
// speedup vs baseline: 1.2369x; 1.1009x over previous
#include <cuda_runtime.h>
#include <math.h>

#define HH 64
#define WW 64
#define BATCH 2
#define CCH 128
#define NPIX (BATCH*HH*WW)
#define KA 624   // unified K: 496 score cols (4cc x 124) + 128 q cols
#define GK 16    // GEMM K-chunk

// ---- scratch ----
__device__ float g_A[(size_t)NPIX * KA];   // [pixel][0..495: scores, 496..623: q]
__device__ float g_B[KA * CCH];            // rows 0..495: wperm, 496..623: m2
__device__ int   g_prep_done;              // monotonic prep-arrival counter

// ============================================================
// Fused kernel: 148 CTAs. CTAs 128..147 do prep (W permute + M2)
// and signal; CTAs 0..127: score phase + split-K GEMM + epilogue.
// ============================================================
#define KV_CC_STRIDE 11664           // 324*36 floats
#define SMEM_SCORE ((4*KV_CC_STRIDE + 64*132) * 4)

typedef unsigned long long ull;
__device__ __forceinline__ ull pk2(float x, float y) {
    ull r;
    asm("mov.b64 %0, {%1,%2};" : "=l"(r) : "f"(x), "f"(y));
    return r;
}
__device__ __forceinline__ void fma2(ull& d, ull a, ull b) {
    asm("fma.rn.f32x2 %0, %1, %2, %3;" : "=l"(d) : "l"(a), "l"(b), "l"(d));
}
__device__ __forceinline__ void upk2(ull v, float& x, float& y) {
    asm("mov.b64 {%0,%1}, %2;" : "=f"(x), "=f"(y) : "l"(v));
}
#define GBAR(id) asm volatile("bar.sync %0, 128;" :: "r"(id) : "memory")

// GEMM-phase smem overlay (floats):
//  [0)      G0: As(2048) + Bs(4096)
//  [6144)   G1: As + Bs
//  [12288)  pub0: G0's mm4..7 partials, 128 slots * 34
//  [16640)  pub1: G1's mm0..3 partials
#define PUB_OFF 12288
#define PUB_STRIDE 4352   // 34*128

template<int PUBBASE>
__device__ __forceinline__ void publish4(ull (&acc)[8][4], float* pub, int lt) {
    #pragma unroll
    for (int mmi = 0; mmi < 4; mmi++)
        #pragma unroll
        for (int n = 0; n < 4; n++)
            *(ull*)&pub[lt * 34 + mmi * 8 + n * 2] = acc[PUBBASE + mmi][n];
}

template<int MYBASE>
__device__ __forceinline__ void epilogue4(
    ull (&acc)[8][4], const float* pubo, const float* s_q,
    const float* __restrict__ bias,
    const float* __restrict__ lng, const float* __restrict__ lnb,
    float* __restrict__ out,
    int b, int h0, int w0, int ty, int lt, int n0, int n1) {
    float bi[8], gg[8], bb[8];
    {
        float4 t0 = *(const float4*)&bias[n0];
        float4 t1 = *(const float4*)&bias[n1];
        bi[0] = t0.x; bi[1] = t0.y; bi[2] = t0.z; bi[3] = t0.w;
        bi[4] = t1.x; bi[5] = t1.y; bi[6] = t1.z; bi[7] = t1.w;
        t0 = *(const float4*)&lng[n0]; t1 = *(const float4*)&lng[n1];
        gg[0] = t0.x; gg[1] = t0.y; gg[2] = t0.z; gg[3] = t0.w;
        gg[4] = t1.x; gg[5] = t1.y; gg[6] = t1.z; gg[7] = t1.w;
        t0 = *(const float4*)&lnb[n0]; t1 = *(const float4*)&lnb[n1];
        bb[0] = t0.x; bb[1] = t0.y; bb[2] = t0.z; bb[3] = t0.w;
        bb[4] = t1.x; bb[5] = t1.y; bb[6] = t1.z; bb[7] = t1.w;
    }
    const float inv128 = 1.0f / 128.0f;
    const float rsqrt2 = 0.70710678118654752f;

    #pragma unroll
    for (int mmi = 0; mmi < 4; mmi++) {
        const int mm = MYBASE + mmi;       // compile-time after unroll
        int pixg = (b * HH + h0 + ty) * WW + w0 + mm;
        int px = ty * 8 + mm;              // local pixel in s_q
        float4 q0 = *(const float4*)&s_q[px * 132 + n0];
        float4 q1 = *(const float4*)&s_q[px * 132 + n1];
        float qv[8] = {q0.x, q0.y, q0.z, q0.w, q1.x, q1.y, q1.z, q1.w};
        float x[8];
        float s1 = 0.f, s2 = 0.f;
        #pragma unroll
        for (int n2 = 0; n2 < 4; n2++) {
            float lo, hi;
            upk2(acc[mm][n2], lo, hi);
            float2 pp = *(const float2*)&pubo[lt * 34 + mmi * 8 + n2 * 2];
            float p0 = lo + pp.x + bi[n2 * 2 + 0];
            float p1 = hi + pp.y + bi[n2 * 2 + 1];
            float e0 = 0.5f * p0 * (1.f + erff(p0 * rsqrt2));
            float e1 = 0.5f * p1 * (1.f + erff(p1 * rsqrt2));
            float x0 = e0 + qv[n2 * 2 + 0];
            float x1 = e1 + qv[n2 * 2 + 1];
            x[n2 * 2 + 0] = x0; x[n2 * 2 + 1] = x1;
            s1 += x0 + x1;
            s2 += x0 * x0 + x1 * x1;
        }
        #pragma unroll
        for (int ofs = 8; ofs >= 1; ofs >>= 1) {
            s1 += __shfl_xor_sync(0xffffffffu, s1, ofs);
            s2 += __shfl_xor_sync(0xffffffffu, s2, ofs);
        }
        float mean = s1 * inv128;
        float var = s2 * inv128 - mean * mean;
        float rstd = rsqrtf(var + 1e-5f);
        *(float4*)&out[(size_t)pixg * CCH + n0] = make_float4(
            (x[0] - mean) * rstd * gg[0] + bb[0],
            (x[1] - mean) * rstd * gg[1] + bb[1],
            (x[2] - mean) * rstd * gg[2] + bb[2],
            (x[3] - mean) * rstd * gg[3] + bb[3]);
        *(float4*)&out[(size_t)pixg * CCH + n1] = make_float4(
            (x[4] - mean) * rstd * gg[4] + bb[4],
            (x[5] - mean) * rstd * gg[5] + bb[5],
            (x[6] - mean) * rstd * gg[6] + bb[6],
            (x[7] - mean) * rstd * gg[7] + bb[7]);
    }
}

__global__ __launch_bounds__(256, 1) void fused_kernel(
    const float* __restrict__ q,
    const float* __restrict__ kv,
    const float* __restrict__ W,
    const float* __restrict__ pos,
    const float* __restrict__ bias,
    const float* __restrict__ lng,
    const float* __restrict__ lnb,
    float* __restrict__ out) {
    extern __shared__ float smem[];
    const int tid = threadIdx.x;
    const int bid = blockIdx.x;

    // ================= PREP CTAs (128..147) =================
    if (bid >= 128) {
        int pid = bid - 128;
        if (pid < 10) {
            // permute W rows (s=4p+cc -> s'=cc*124+p) into g_B[0..495]
            int end = pid * 1600 + 1600;
            if (end > 15872) end = 15872;
            for (int t = pid * 1600 + tid; t < end; t += 256) {
                int row = t >> 5, c4 = t & 31;
                int cc = row / 124, p = row - cc * 124;
                float4 v = make_float4(0.f, 0.f, 0.f, 0.f);
                if (p < 121) v = ((const float4*)(W + (size_t)(4 * p + cc) * CCH))[c4];
                ((float4*)(g_B + (size_t)row * CCH))[c4] = v;
            }
        } else {
            // M2 rows: g_B[496+c][o] = sum_p pos[(s0+p)*32+cm] * W[(s0+p)*128+o]
            int o = tid & 127, ch = tid >> 7;
            int cb = (pid - 10) * 13;
            for (int ci = ch; ci < 13; ci += 2) {
                int c = cb + ci;
                if (c >= 128) break;
                int g = c >> 5, cm = c & 31;
                int s0 = 121 * g;
                float a0 = 0.f, a1 = 0.f, a2 = 0.f, a3 = 0.f;
                int p = 0;
                for (; p + 4 <= 121; p += 4) {
                    a0 += pos[(s0 + p + 0) * 32 + cm] * W[(size_t)(s0 + p + 0) * CCH + o];
                    a1 += pos[(s0 + p + 1) * 32 + cm] * W[(size_t)(s0 + p + 1) * CCH + o];
                    a2 += pos[(s0 + p + 2) * 32 + cm] * W[(size_t)(s0 + p + 2) * CCH + o];
                    a3 += pos[(s0 + p + 3) * 32 + cm] * W[(size_t)(s0 + p + 3) * CCH + o];
                }
                for (; p < 121; p++)
                    a0 += pos[(s0 + p) * 32 + cm] * W[(size_t)(s0 + p) * CCH + o];
                g_B[(size_t)(496 + c) * CCH + o] = (a0 + a1) + (a2 + a3);
            }
        }
        __syncthreads();
        __threadfence();
        if (tid == 0) atomicAdd(&g_prep_done, 1);
        return;
    }

    // ================= WORKER CTAs (0..127) =================
    float* s_kv = smem;
    float* s_q  = smem + 4 * KV_CC_STRIDE;
    const int b = bid >> 6;
    const int h0 = ((bid >> 3) & 7) * 8;
    const int w0 = (bid & 7) * 8;

    // ---- staging ----
    for (int idx = tid; idx < 324 * 32; idx += 256) {
        int pos_ = idx >> 5, c4 = idx & 31;
        int r = pos_ / 18, xc = pos_ - r * 18;
        int y = h0 - 5 + r, x = w0 - 5 + xc;
        float4 v = make_float4(0.f, 0.f, 0.f, 0.f);
        if ((unsigned)y < HH && (unsigned)x < WW)
            v = ((const float4*)(kv + (size_t)((b * HH + y) * WW + x) * CCH))[c4];
        int cc = c4 >> 3, d4 = c4 & 7;
        *(float4*)&s_kv[cc * KV_CC_STRIDE + pos_ * 36 + d4 * 4] = v;
    }
    for (int idx = tid; idx < 64 * 32; idx += 256) {
        int px = idx >> 5, c4 = idx & 31;
        int ph = px >> 3, pw = px & 7;
        int pixg = (b * HH + h0 + ph) * WW + (w0 + pw);
        float4 v = ((const float4*)(q + (size_t)pixg * CCH))[c4];
        *(float4*)&s_q[px * 132 + c4 * 4] = v;
        *(float4*)&g_A[(size_t)pixg * KA + 496 + c4 * 4] = v;
    }
    __syncthreads();

    // ================= SCORE PHASE (quads; transpose-reduce stores) =================
    {
        const int dg   = tid & 3;
        const int cc   = (tid >> 2) & 3;
        const int quad = tid >> 4;                  // 0..15
        const int qrow = quad >> 1, qcol = quad & 1;
        const int pxb  = qrow * 8 + qcol * 4;
        const int pixg0 = (b * HH + h0 + qrow) * WW + (w0 + qcol * 4);
        const float* ccb = s_kv + cc * KV_CC_STRIDE;
        const bool dlow = (dg & 2) == 0;
        const bool deven = (dg & 1) == 0;

        #pragma unroll 1
        for (int i = 0; i < 11; i++) {
            float acc[4][11];
            #pragma unroll
            for (int k = 0; k < 4; k++)
                #pragma unroll
                for (int j = 0; j < 11; j++) acc[k][j] = 0.f;

            int gA = (44 * i) / 121;
            bool cross = (i == 2) | (i == 5) | (i == 8);
            int sbase = 44 * i + cc;
            int thr2 = 121 * (gA + 1);

            #pragma unroll 1
            for (int hd = 0; hd < 2; hd++) {
                int d4 = dg + 4 * hd;
                float4 qA[4];
                #pragma unroll
                for (int k = 0; k < 4; k++)
                    qA[k] = *(const float4*)&s_q[(pxb + k) * 132 + gA * 32 + d4 * 4];
                float4 win[14];
                const float* rowp = ccb + ((qrow + i) * 18 + qcol * 4) * 36 + d4 * 4;
                #pragma unroll
                for (int x = 0; x < 14; x++) win[x] = *(const float4*)&rowp[x * 36];

                if (!cross) {
                    #pragma unroll
                    for (int j = 0; j < 11; j++) {
                        #pragma unroll
                        for (int k = 0; k < 4; k++) {
                            float4 kvv = win[j + k];
                            acc[k][j] += kvv.x * qA[k].x + kvv.y * qA[k].y
                                       + kvv.z * qA[k].z + kvv.w * qA[k].w;
                        }
                    }
                } else {
                    float4 qB[4];
                    #pragma unroll
                    for (int k = 0; k < 4; k++)
                        qB[k] = *(const float4*)&s_q[(pxb + k) * 132 + (gA + 1) * 32 + d4 * 4];
                    #pragma unroll
                    for (int j = 0; j < 11; j++) {
                        bool sel = (sbase + 4 * j) >= thr2;
                        #pragma unroll
                        for (int k = 0; k < 4; k++) {
                            float4 qv = sel ? qB[k] : qA[k];
                            float4 kvv = win[j + k];
                            acc[k][j] += kvv.x * qv.x + kvv.y * qv.y
                                       + kvv.z * qv.z + kvv.w * qv.w;
                        }
                    }
                }
            }

            // ---- reducing transpose across dg lanes: lane dg ends with pixel dg ----
            float k0[11], k1[11];
            #pragma unroll
            for (int j = 0; j < 11; j++) {
                float s0 = dlow ? acc[2][j] : acc[0][j];
                float s1 = dlow ? acc[3][j] : acc[1][j];
                float r0 = __shfl_xor_sync(0xffffffffu, s0, 2);
                float r1 = __shfl_xor_sync(0xffffffffu, s1, 2);
                k0[j] = (dlow ? acc[0][j] : acc[2][j]) + r0;
                k1[j] = (dlow ? acc[1][j] : acc[3][j]) + r1;
            }
            float* outp = g_A + (size_t)(pixg0 + dg) * KA + cc * 124 + 11 * i;
            #pragma unroll
            for (int j = 0; j < 11; j++) {
                float s = deven ? k1[j] : k0[j];
                float r = __shfl_xor_sync(0xffffffffu, s, 1);
                outp[j] = (deven ? k0[j] : k1[j]) + r;
            }
        }
    }
    __syncthreads();   // scores + q mirror in g_A visible; smem (except s_q) free

    // ---- wait for prep (off critical path: prep finished ~30us ago) ----
    if (tid == 0) {
        while (atomicAdd(&g_prep_done, 0) < 20) { }
    }
    __syncthreads();

    // ================= GEMM PHASE (two 128-thread split-K groups) =================
    const int g  = tid >> 7;          // group 0/1
    const int lt = tid & 127;
    const int tx = lt & 15, ty = lt >> 4;
    const int n0 = tx * 4, n1 = 64 + tx * 4;
    const int pixL = lt >> 1, halfk = (lt & 1) * 8;
    const int brow = lt >> 5, bcol = (lt & 31) * 4;
    const int kbeg = g ? 320 : 0;
    const int nk   = g ? 19 : 20;     // 320 + 304 = 624
    const int barid = 1 + g;

    float* as_ = smem + g * 6144;           // [2][16][64]
    float* bs_ = smem + g * 6144 + 2048;    // [2][16][128]

    const float* Arow = g_A + (size_t)((b * HH + h0 + (pixL >> 3)) * WW + w0 + (pixL & 7)) * KA + kbeg;
    const float* B = g_B + (size_t)kbeg * CCH;

    ull acc[8][4];
    #pragma unroll
    for (int m = 0; m < 8; m++)
        #pragma unroll
        for (int n = 0; n < 4; n++) acc[m][n] = 0ULL;

    float4 av0 = *(const float4*)&Arow[halfk];
    float4 av1 = *(const float4*)&Arow[halfk + 4];
    float4 bv[4];
    #pragma unroll
    for (int r = 0; r < 4; r++)
        bv[r] = *(const float4*)&B[(size_t)(brow + 4 * r) * CCH + bcol];

    int buf = 0;
    as_[(halfk + 0) * 64 + pixL] = av0.x;
    as_[(halfk + 1) * 64 + pixL] = av0.y;
    as_[(halfk + 2) * 64 + pixL] = av0.z;
    as_[(halfk + 3) * 64 + pixL] = av0.w;
    as_[(halfk + 4) * 64 + pixL] = av1.x;
    as_[(halfk + 5) * 64 + pixL] = av1.y;
    as_[(halfk + 6) * 64 + pixL] = av1.z;
    as_[(halfk + 7) * 64 + pixL] = av1.w;
    #pragma unroll
    for (int r = 0; r < 4; r++)
        *(float4*)&bs_[(brow + 4 * r) * 128 + bcol] = bv[r];
    GBAR(barid);

    for (int kc = 0; kc < nk; kc++) {
        bool more = (kc + 1 < nk);
        if (more) {
            int kn = (kc + 1) * GK;
            av0 = *(const float4*)&Arow[kn + halfk];
            av1 = *(const float4*)&Arow[kn + halfk + 4];
            #pragma unroll
            for (int r = 0; r < 4; r++)
                bv[r] = *(const float4*)&B[(size_t)(kn + brow + 4 * r) * CCH + bcol];
        }
        const float* asb = as_ + buf * 1024;
        const float* bsb = bs_ + buf * 2048;
        #pragma unroll
        for (int k = 0; k < GK; k++) {
            float4 a0 = *(const float4*)&asb[k * 64 + ty * 8];
            float4 a1 = *(const float4*)&asb[k * 64 + ty * 8 + 4];
            ulonglong2 bq0 = *(const ulonglong2*)&bsb[k * 128 + n0];
            ulonglong2 bq1 = *(const ulonglong2*)&bsb[k * 128 + n1];
            ull bp[4] = {bq0.x, bq0.y, bq1.x, bq1.y};
            float am[8] = {a0.x, a0.y, a0.z, a0.w, a1.x, a1.y, a1.z, a1.w};
            #pragma unroll
            for (int m = 0; m < 8; m++) {
                ull ad = pk2(am[m], am[m]);
                #pragma unroll
                for (int n = 0; n < 4; n++) fma2(acc[m][n], ad, bp[n]);
            }
        }
        if (more) {
            int nb = buf ^ 1;
            float* asn = as_ + nb * 1024;
            float* bsn = bs_ + nb * 2048;
            asn[(halfk + 0) * 64 + pixL] = av0.x;
            asn[(halfk + 1) * 64 + pixL] = av0.y;
            asn[(halfk + 2) * 64 + pixL] = av0.z;
            asn[(halfk + 3) * 64 + pixL] = av0.w;
            asn[(halfk + 4) * 64 + pixL] = av1.x;
            asn[(halfk + 5) * 64 + pixL] = av1.y;
            asn[(halfk + 6) * 64 + pixL] = av1.z;
            asn[(halfk + 7) * 64 + pixL] = av1.w;
            #pragma unroll
            for (int r = 0; r < 4; r++)
                *(float4*)&bsn[(brow + 4 * r) * 128 + bcol] = bv[r];
            GBAR(barid);
            buf = nb;
        }
    }

    // ---- publish (compile-time indices): G0 -> mm4..7, G1 -> mm0..3 ----
    if (g == 0) publish4<4>(acc, smem + PUB_OFF,              lt);
    else        publish4<0>(acc, smem + PUB_OFF + PUB_STRIDE, lt);
    __syncthreads();

    // ---- epilogue (compile-time indices): G0 -> mm0..3, G1 -> mm4..7 ----
    if (g == 0)
        epilogue4<0>(acc, smem + PUB_OFF + PUB_STRIDE, s_q, bias, lng, lnb, out,
                     b, h0, w0, ty, lt, n0, n1);
    else
        epilogue4<4>(acc, smem + PUB_OFF,              s_q, bias, lng, lnb, out,
                     b, h0, w0, ty, lt, n0, n1);
}

// ============================================================
extern "C" void kernel_launch(void* const* d_in, const int* in_sizes, int n_in,
                              void* d_out, int out_size) {
    const float* q    = (const float*)d_in[0];
    const float* kv   = (const float*)d_in[1];
    const float* pos  = (const float*)d_in[2];
    const float* W    = (const float*)d_in[3];
    const float* bias = (const float*)d_in[4];
    const float* lng  = (const float*)d_in[5];
    const float* lnb  = (const float*)d_in[6];
    float* out = (float*)d_out;

    static int smem_set = 0;
    if (!smem_set) {
        cudaFuncSetAttribute(fused_kernel,
                             cudaFuncAttributeMaxDynamicSharedMemorySize, SMEM_SCORE);
        smem_set = 1;
    }

    fused_kernel<<<148, 256, SMEM_SCORE>>>(q, kv, W, pos, bias, lng, lnb, out);
}